// round 3
// baseline (speedup 1.0000x reference)
#include <cuda_runtime.h>
#include <math.h>

#define D 128
#define N_MID 6
#define N_MAX 131072

// ---------------- preprocessed weights (device globals, no runtime alloc) ----------------
__device__ __align__(16) float d_AU0[2][D];           // [k][o]  k=0:x, k=1:theta
__device__ __align__(16) float d_B0[D];
__device__ __align__(16) float d_W0[D * D];           // [k][o] = softmax(w0)[o][k]
__device__ __align__(16) float d_AUM[N_MID][D * D];   // [k][o] = exp(laM[o])*softmax(uM)[o][k]
__device__ __align__(16) float d_BM[N_MID][D];
__device__ __align__(16) float d_WM[N_MID][D * D];    // [k][o]
__device__ __align__(16) float d_auL[D];
__device__ float d_bL;
__device__ __align__(16) float d_theta[N_MAX];

__device__ __forceinline__ float sigmoidf(float x) {
    return __fdividef(1.0f, 1.0f + __expf(-x));
}

// ---------------- weight preprocessing: row softmax + exp(log_a) folding ----------------
__global__ void prep_kernel(const float* __restrict__ u0, const float* __restrict__ w0,
                            const float* __restrict__ la0, const float* __restrict__ b0,
                            const float* __restrict__ uM, const float* __restrict__ wM,
                            const float* __restrict__ laM, const float* __restrict__ bM,
                            const float* __restrict__ uL, const float* __restrict__ laL,
                            const float* __restrict__ bL) {
    const int b = blockIdx.x;
    const int o = threadIdx.x;  // 128 threads
    if (b == 0) {
        // first layer: softmax over 2 inputs, scaled by exp(la0)
        float v0 = u0[o * 2 + 0], v1 = u0[o * 2 + 1];
        float m = fmaxf(v0, v1);
        float e0 = expf(v0 - m), e1 = expf(v1 - m);
        float a = expf(la0[o]);
        float inv = a / (e0 + e1);
        d_AU0[0][o] = e0 * inv;
        d_AU0[1][o] = e1 * inv;
        d_B0[o] = b0[o];
        if (o == 0) {
            // last layer: uL [1,128] row-softmax, times exp(laL). softmax(wL[1,1]) == 1.
            float mm = -1e30f;
            for (int k = 0; k < D; k++) mm = fmaxf(mm, uL[k]);
            float s = 0.f;
            for (int k = 0; k < D; k++) s += expf(uL[k] - mm);
            float inv2 = expf(laL[0]) / s;
            for (int k = 0; k < D; k++) d_auL[k] = expf(uL[k] - mm) * inv2;
            d_bL = bL[0];
        }
    } else if (b == 1) {
        const float* row = w0 + o * D;
        float m = -1e30f;
        for (int k = 0; k < D; k++) m = fmaxf(m, row[k]);
        float s = 0.f;
        for (int k = 0; k < D; k++) s += expf(row[k] - m);
        float inv = 1.0f / s;
        for (int k = 0; k < D; k++) d_W0[k * D + o] = expf(row[k] - m) * inv;
    } else if (b < 2 + N_MID) {
        const int mI = b - 2;
        const float* row = uM + mI * D * D + o * D;
        float m = -1e30f;
        for (int k = 0; k < D; k++) m = fmaxf(m, row[k]);
        float s = 0.f;
        for (int k = 0; k < D; k++) s += expf(row[k] - m);
        float inv = expf(laM[mI * D + o]) / s;
        for (int k = 0; k < D; k++) d_AUM[mI][k * D + o] = expf(row[k] - m) * inv;
        d_BM[mI][o] = bM[mI * D + o];
    } else {
        const int mI = b - 2 - N_MID;
        const float* row = wM + mI * D * D + o * D;
        float m = -1e30f;
        for (int k = 0; k < D; k++) m = fmaxf(m, row[k]);
        float s = 0.f;
        for (int k = 0; k < D; k++) s += expf(row[k] - m);
        float inv = 1.0f / s;
        for (int k = 0; k < D; k++) d_WM[mI][k * D + o] = expf(row[k] - m) * inv;
    }
}

// ---------------- feature MLP: theta[i] = MLP_1_50_50_1(fy0[i]) ----------------
__global__ void __launch_bounds__(256) theta_kernel(
    const float* __restrict__ fy0,
    const float* __restrict__ W1, const float* __restrict__ b1,
    const float* __restrict__ W2, const float* __restrict__ b2,
    const float* __restrict__ W3, const float* __restrict__ b3, int n) {
    __shared__ float sW1[50], sb1[50], sW2[2500], sb2[50], sW3[50];
    const int tid = threadIdx.x;
    if (tid < 50) { sW1[tid] = W1[tid]; sb1[tid] = b1[tid]; sb2[tid] = b2[tid]; sW3[tid] = W3[tid]; }
    for (int i = tid; i < 2500; i += 256) sW2[i] = W2[i];
    __syncthreads();
    const int i = blockIdx.x * 256 + tid;
    if (i >= n) return;
    const float v = fy0[i];
    float h1[50];
#pragma unroll
    for (int j = 0; j < 50; j++) h1[j] = fmaxf(fmaf(sW1[j], v, sb1[j]), 0.0f);
    float th = b3[0];
    for (int j = 0; j < 50; j++) {
        const float* wr = sW2 + j * 50;
        float a0 = sb2[j], a1 = 0.f, a2 = 0.f, a3 = 0.f;
#pragma unroll
        for (int k = 0; k < 48; k += 4) {
            a0 = fmaf(wr[k + 0], h1[k + 0], a0);
            a1 = fmaf(wr[k + 1], h1[k + 1], a1);
            a2 = fmaf(wr[k + 2], h1[k + 2], a2);
            a3 = fmaf(wr[k + 3], h1[k + 3], a3);
        }
        a0 = fmaf(wr[48], h1[48], a0);
        a1 = fmaf(wr[49], h1[49], a1);
        float acc = (a0 + a1) + (a2 + a3);
        th = fmaf(sW3[j], fmaxf(acc, 0.0f), th);
    }
    d_theta[i] = th;
}

// ---------------- fused 128x128x128 SGEMM core (A, C transposed k-major in SMEM) ----------------
// C[o][r] = (ACT ? sigmoid(sum_k A[k][r]*B[k][o] + bias[o]) : sum_k A[k][r]*B[k][o])
template <bool ACT>
__device__ __forceinline__ void gemm128(const float* __restrict__ A,
                                        const float* __restrict__ Bglob,
                                        float* __restrict__ C,
                                        const float* __restrict__ bias,
                                        float* __restrict__ sW) {
    const int tid = threadIdx.x;
    __syncthreads();  // prior consumers of sW / prior writes to C done
    {
        const float4* src = (const float4*)Bglob;
        float4* dst = (float4*)sW;
#pragma unroll
        for (int i = 0; i < 16; i++) dst[tid + 256 * i] = src[tid + 256 * i];
    }
    __syncthreads();
    const int tx = tid & 15;   // row-group (fast across lanes -> coalesced SMEM)
    const int ty = tid >> 4;   // col-group
    const float* Ap = A + tx * 8;
    const float* Bp = sW + ty * 8;
    float acc[8][8];
#pragma unroll
    for (int i = 0; i < 8; i++)
#pragma unroll
        for (int j = 0; j < 8; j++) acc[i][j] = 0.0f;

#pragma unroll 8
    for (int k = 0; k < D; k++) {
        float4 a0 = *(const float4*)(Ap + k * D);
        float4 a1 = *(const float4*)(Ap + k * D + 4);
        float4 b0 = *(const float4*)(Bp + k * D);
        float4 b1 = *(const float4*)(Bp + k * D + 4);
        float av[8] = {a0.x, a0.y, a0.z, a0.w, a1.x, a1.y, a1.z, a1.w};
        float bv[8] = {b0.x, b0.y, b0.z, b0.w, b1.x, b1.y, b1.z, b1.w};
#pragma unroll
        for (int i = 0; i < 8; i++)
#pragma unroll
            for (int j = 0; j < 8; j++) acc[i][j] = fmaf(av[i], bv[j], acc[i][j]);
    }

#pragma unroll
    for (int j = 0; j < 8; j++) {
        const int o = ty * 8 + j;
        float outv[8];
        if (ACT) {
            const float bj = bias[o];
#pragma unroll
            for (int i = 0; i < 8; i++) outv[i] = sigmoidf(acc[i][j] + bj);
        } else {
#pragma unroll
            for (int i = 0; i < 8; i++) outv[i] = acc[i][j];
        }
        *(float4*)(C + o * D + tx * 8) = make_float4(outv[0], outv[1], outv[2], outv[3]);
        *(float4*)(C + o * D + tx * 8 + 4) = make_float4(outv[4], outv[5], outv[6], outv[7]);
    }
}

// ---------------- fully fused per-128-row-slab kernel ----------------
__global__ void __launch_bounds__(256, 1) fused_kernel(const float* __restrict__ x,
                                                       float* __restrict__ out, int n) {
    extern __shared__ float smem[];
    float* hA = smem;             // [k][r] 128x128
    float* hB = smem + 16384;     // [k][r]
    float* sW = smem + 32768;     // weight stage [k][o]
    float* sx = smem + 49152;     // 128
    float* sth = sx + 128;        // 128

    const int tid = threadIdx.x;
    const int r0 = blockIdx.x * D;
    if (tid < D) { sx[tid] = x[r0 + tid]; sth[tid] = d_theta[r0 + tid]; }
    __syncthreads();

    // first layer (in=2): sigmoid(x*au0 + theta*au1 + b0), stored transposed into hA[o][r]
#pragma unroll
    for (int it = 0; it < 64; it++) {
        const int idx = tid + it * 256;
        const int o = idx >> 7, r = idx & 127;
        float inner = fmaf(sx[r], d_AU0[0][o], fmaf(sth[r], d_AU0[1][o], d_B0[o]));
        hA[o * D + r] = sigmoidf(inner);
    }

    // layer0 W matmul (no activation)
    gemm128<false>(hA, d_W0, hB, nullptr, sW);

    // six middle layers
#pragma unroll 1
    for (int m = 0; m < N_MID; m++) {
        gemm128<true>(hB, d_AUM[m], hA, d_BM[m], sW);
        gemm128<false>(hA, d_WM[m], hB, nullptr, sW);
    }

    __syncthreads();
    // last layer: out[r] = sigmoid(sum_k hB[k][r]*auL[k] + bL)
    if (tid < D) {
        float acc = d_bL;
#pragma unroll 8
        for (int k = 0; k < D; k++) acc = fmaf(hB[k * D + tid], d_auL[k], acc);
        out[r0 + tid] = sigmoidf(acc);
    }
}

// ---------------- launch ----------------
extern "C" void kernel_launch(void* const* d_in, const int* in_sizes, int n_in,
                              void* d_out, int out_size) {
    const float* x   = (const float*)d_in[0];
    const float* fy0 = (const float*)d_in[1];
    const float* u0  = (const float*)d_in[2];
    const float* w0  = (const float*)d_in[3];
    const float* la0 = (const float*)d_in[4];
    const float* b0  = (const float*)d_in[5];
    const float* uM  = (const float*)d_in[6];
    const float* wM  = (const float*)d_in[7];
    const float* laM = (const float*)d_in[8];
    const float* bM  = (const float*)d_in[9];
    const float* uL  = (const float*)d_in[10];
    // d_in[11] = wL: softmax of a [1,1] row is exactly 1.0 -> multiplicative identity
    const float* laL = (const float*)d_in[12];
    const float* bL  = (const float*)d_in[13];
    const float* W1  = (const float*)d_in[14];
    const float* b1  = (const float*)d_in[15];
    const float* W2  = (const float*)d_in[16];
    const float* b2  = (const float*)d_in[17];
    const float* W3  = (const float*)d_in[18];
    const float* b3  = (const float*)d_in[19];
    float* out = (float*)d_out;
    const int n = in_sizes[0];

    const int smem_bytes = (16384 * 3 + 256) * 4;  // 197632 B
    cudaFuncSetAttribute(fused_kernel, cudaFuncAttributeMaxDynamicSharedMemorySize, smem_bytes);

    prep_kernel<<<2 + 2 * N_MID, 128>>>(u0, w0, la0, b0, uM, wM, laM, bM, uL, laL, bL);
    theta_kernel<<<(n + 255) / 256, 256>>>(fy0, W1, b1, W2, b2, W3, b3, n);
    fused_kernel<<<n / D, 256, smem_bytes>>>(x, out, n);
}

// round 5
// speedup vs baseline: 4.3542x; 4.3542x over previous
#include <cuda_runtime.h>
#include <math.h>
#include <stdint.h>

#define D 128
#define NSTAGE 6

// ===================== device globals =====================
__device__ __align__(16) float d_AUMf[6][D * D];     // exp(la)*softmax(uM), [o][j]
__device__ __align__(16) float d_Wf[7][D * D];       // softmax rows: [0]=w0, [1..6]=wM
__device__ __align__(128) float d_Gimg[NSTAGE][D * D]; // G_m packed in B-fragment order, tf32
__device__ float d_au0x[D], d_au0t[D], d_b0v[D];
__device__ float d_bMv[6][D];
__device__ float d_auLv[D];
__device__ float d_vfin[D];
__device__ float d_bLv;

// ===================== helpers =====================
__device__ __forceinline__ uint32_t smem_u32(const void* p) {
    uint32_t a;
    asm("{ .reg .u64 t; cvta.to.shared.u64 t, %1; cvt.u32.u64 %0, t; }" : "=r"(a) : "l"(p));
    return a;
}
__device__ __forceinline__ uint32_t f2tf32(float x) {
    uint32_t u; asm("cvt.rna.tf32.f32 %0, %1;" : "=r"(u) : "f"(x)); return u;
}
__device__ __forceinline__ float tanh_ap(float x) {
    float y; asm("tanh.approx.f32 %0, %1;" : "=f"(y) : "f"(x)); return y;
}
__device__ __forceinline__ float sigmoid_fast(float x) {
    return fmaf(tanh_ap(0.5f * x), 0.5f, 0.5f);
}

#define MBARRIER_INIT(mbar, count) \
    asm volatile("mbarrier.init.shared.b64 [%0], %1;" :: "r"((uint32_t)(mbar)), "r"((uint32_t)(count)) : "memory")
#define MBARRIER_EXPECT_TX(mbar, bytes) \
    asm volatile("mbarrier.arrive.expect_tx.shared.b64 _, [%0], %1;" :: "r"((uint32_t)(mbar)), "r"((uint32_t)(bytes)) : "memory")
#define MBARRIER_WAIT_PARITY(mbar, parity) do { \
    uint32_t _m = (uint32_t)(mbar); uint32_t _p = (uint32_t)(parity); uint32_t _d; \
    asm volatile("{\n\t.reg .pred p;\n\t" \
        "mbarrier.try_wait.parity.acquire.cta.shared::cta.b64 p, [%1], %2;\n\t" \
        "selp.b32 %0, 1, 0, p;\n\t}" : "=r"(_d) : "r"(_m), "r"(_p) : "memory"); \
    if (!_d) { \
        asm volatile("{\n\t.reg .pred P1;\n\t" \
            "WAIT_LOOP_%=:\n\t" \
            "mbarrier.try_wait.parity.acquire.cta.shared::cta.b64 P1, [%0], %1, 0x989680;\n\t" \
            "@P1 bra.uni WAIT_DONE_%=;\n\t" \
            "bra.uni WAIT_LOOP_%=;\n\t" \
            "WAIT_DONE_%=:\n\t}" :: "r"(_m), "r"(_p) : "memory"); \
    } \
} while (0)

#define BULK_G2S(smem, gptr, bytes, mbar) \
    asm volatile("cp.async.bulk.shared::cluster.global.mbarrier::complete_tx::bytes [%0], [%1], %2, [%3];" \
        :: "r"((uint32_t)(smem)), "l"(gptr), "r"((uint32_t)(bytes)), "r"((uint32_t)(mbar)) : "memory")

// mma.sync m16n8k8 tf32 (arch-agnostic HMMA path; tcgen05 is not available on this
// toolchain's plain sm_103 PTX target).
__device__ __forceinline__ void mma8(float* d, const uint32_t* a, uint32_t b0, uint32_t b1) {
    asm volatile(
        "mma.sync.aligned.m16n8k8.row.col.f32.tf32.tf32.f32 "
        "{%0,%1,%2,%3}, {%4,%5,%6,%7}, {%8,%9}, {%0,%1,%2,%3};"
        : "+f"(d[0]), "+f"(d[1]), "+f"(d[2]), "+f"(d[3])
        : "r"(a[0]), "r"(a[1]), "r"(a[2]), "r"(a[3]), "r"(b0), "r"(b1));
}

// ===================== prep1: warp-per-row softmax / folding =====================
__device__ __forceinline__ void warp_softmax_row(const float* __restrict__ row,
                                                 float* __restrict__ dst,
                                                 float scale, int lane) {
    float v[4];
#pragma unroll
    for (int q = 0; q < 4; q++) v[q] = row[lane + 32 * q];
    float m = fmaxf(fmaxf(v[0], v[1]), fmaxf(v[2], v[3]));
#pragma unroll
    for (int o = 16; o > 0; o >>= 1) m = fmaxf(m, __shfl_xor_sync(~0u, m, o));
    float e[4]; float s = 0.f;
#pragma unroll
    for (int q = 0; q < 4; q++) { e[q] = expf(v[q] - m); s += e[q]; }
#pragma unroll
    for (int o = 16; o > 0; o >>= 1) s += __shfl_xor_sync(~0u, s, o);
    const float inv = scale / s;
#pragma unroll
    for (int q = 0; q < 4; q++) dst[lane + 32 * q] = e[q] * inv;
}

__global__ void prep1_kernel(const float* __restrict__ u0, const float* __restrict__ w0,
                             const float* __restrict__ la0, const float* __restrict__ b0,
                             const float* __restrict__ uM, const float* __restrict__ wM,
                             const float* __restrict__ laM, const float* __restrict__ bM,
                             const float* __restrict__ uL, const float* __restrict__ laL,
                             const float* __restrict__ bL) {
    const int gw = (blockIdx.x * blockDim.x + threadIdx.x) >> 5;
    const int lane = threadIdx.x & 31;
    if (gw < 128) {
        warp_softmax_row(w0 + gw * D, d_Wf[0] + gw * D, 1.0f, lane);
    } else if (gw < 896) {
        const int m = (gw - 128) >> 7, o = (gw - 128) & 127;
        warp_softmax_row(uM + (m * D + o) * D, d_AUMf[m] + o * D, expf(laM[m * D + o]), lane);
        if (lane == 0) d_bMv[m][o] = bM[m * D + o];
    } else if (gw < 1664) {
        const int m = (gw - 896) >> 7, o = (gw - 896) & 127;
        warp_softmax_row(wM + (m * D + o) * D, d_Wf[1 + m] + o * D, 1.0f, lane);
    } else if (gw == 1664) {
#pragma unroll
        for (int q = 0; q < 4; q++) {
            const int o = lane + 32 * q;
            float v0 = u0[o * 2 + 0], v1 = u0[o * 2 + 1];
            float m = fmaxf(v0, v1);
            float e0 = expf(v0 - m), e1 = expf(v1 - m);
            float inv = expf(la0[o]) / (e0 + e1);
            d_au0x[o] = e0 * inv;
            d_au0t[o] = e1 * inv;
            d_b0v[o] = b0[o];
        }
    } else if (gw == 1665) {
        warp_softmax_row(uL, d_auLv, expf(laL[0]), lane);
        if (lane == 0) d_bLv = bL[0];
    }
}

// ===================== prep2: G_m = AUM[m] @ Wf[m], tf32, B-fragment-packed; v =====================
__global__ void prep2_kernel() {
    extern __shared__ float sh[];   // 16384 (W) + 2048 (AU rows)
    float* sW = sh;
    float* sAU = sh + 16384;
    const int b = blockIdx.x, tid = threadIdx.x;
    if (b < 48) {
        const int m = b >> 3;
        const int oc = (b & 7) * 16;
        for (int i = tid; i < 16384; i += 256) sW[i] = d_Wf[m][i];
        for (int i = tid; i < 2048; i += 256) sAU[i] = d_AUMf[m][oc * D + i];
        __syncthreads();
#pragma unroll 1
        for (int q = 0; q < 8; q++) {
            const int idx = tid + q * 256;
            const int ol = idx >> 7, i = idx & 127;
            const float* au = sAU + ol * D;
            float acc = 0.f;
#pragma unroll 8
            for (int j = 0; j < D; j++) acc = fmaf(au[j], sW[j * D + i], acc);
            const int o = oc + ol;
            // B-fragment pack: value G[o=n][i=k] for mma.sync m16n8k8 tf32
            const int t = o >> 3, gg = o & 7;
            const int kp = i >> 4, ks1 = (i >> 3) & 1;
            const int c = i & 3, half = (i >> 2) & 1;
            const int flat = (((t * 8 + kp) * 32) + gg * 4 + c) * 4 + ks1 * 2 + half;
            d_Gimg[m][flat] = __uint_as_float(f2tf32(acc));
        }
    } else {
        if (tid < D) {
            float acc = 0.f;
            for (int j = 0; j < D; j++) acc = fmaf(d_auLv[j], d_Wf[6][j * D + tid], acc);
            d_vfin[tid] = acc;
        }
    }
}

// ===================== fused kernel: theta MLP + first layer + 6 tf32 mma stages + final =====================
__global__ void __launch_bounds__(256, 1) fused_kernel(
    const float* __restrict__ x, const float* __restrict__ fy0,
    const float* __restrict__ W1, const float* __restrict__ b1,
    const float* __restrict__ W2, const float* __restrict__ b2,
    const float* __restrict__ W3, const float* __restrict__ b3,
    float* __restrict__ out, int n) {
    extern __shared__ float dyn[];  // [0,16384): act  [16384,32768): wbuf0  [32768,49152): wbuf1
    __shared__ float s_c[1281];     // au0x|au0t|b0|bM[6]|v|bL
    __shared__ float s_mlp[2701];   // W1|b1|b2|W3|W2|b3
    __shared__ float s_x[128], s_fy[128], s_th[128];
    __shared__ __align__(8) unsigned long long s_bar[2];

    const int tid = threadIdx.x;
    const int w = tid >> 5, lane = tid & 31;
    const int g = lane >> 2, c = lane & 3;
    const uint32_t mbW0 = smem_u32(&s_bar[0]);
    const uint32_t mbW1 = smem_u32(&s_bar[1]);
    const uint32_t dynb = smem_u32(dyn);

    if (tid == 0) {
        MBARRIER_INIT(mbW0, 1); MBARRIER_INIT(mbW1, 1);
        MBARRIER_EXPECT_TX(mbW0, 65536);
        BULK_G2S(dynb + 65536u, &d_Gimg[0][0], 65536, mbW0);
        MBARRIER_EXPECT_TX(mbW1, 65536);
        BULK_G2S(dynb + 131072u, &d_Gimg[1][0], 65536, mbW1);
        s_c[1280] = d_bLv;
        s_mlp[2700] = b3[0];
    }
    {
        const int gi = blockIdx.x * 128 + tid;
        if (tid < 128) {
            const bool ok = gi < n;
            s_x[tid] = ok ? x[gi] : 0.f;
            s_fy[tid] = ok ? fy0[gi] : 0.f;
            s_c[tid] = d_au0x[tid];
            s_c[128 + tid] = d_au0t[tid];
            s_c[256 + tid] = d_b0v[tid];
#pragma unroll
            for (int m = 0; m < 6; m++) s_c[384 + m * 128 + tid] = d_bMv[m][tid];
            s_c[1152 + tid] = d_vfin[tid];
        }
        if (tid < 50) {
            s_mlp[tid] = W1[tid]; s_mlp[50 + tid] = b1[tid];
            s_mlp[100 + tid] = b2[tid]; s_mlp[150 + tid] = W3[tid];
        }
        for (int i = tid; i < 2500; i += 256) s_mlp[200 + i] = W2[i];
    }
    __syncthreads();

    // ---- theta MLP: 2 threads per row ----
    {
        const int rl = tid >> 1, hf = tid & 1;
        const float fv = s_fy[rl];
        float h1[50];
#pragma unroll
        for (int j = 0; j < 50; j++) h1[j] = fmaxf(fmaf(s_mlp[j], fv, s_mlp[50 + j]), 0.f);
        float part = 0.f;
        const int j0 = hf * 25;
#pragma unroll 1
        for (int j = j0; j < j0 + 25; j++) {
            const float* wr = s_mlp + 200 + j * 50;
            float a0 = s_mlp[100 + j], a1 = 0.f;
#pragma unroll
            for (int k = 0; k < 50; k += 2) { a0 = fmaf(wr[k], h1[k], a0); a1 = fmaf(wr[k + 1], h1[k + 1], a1); }
            part = fmaf(s_mlp[150 + j], fmaxf(a0 + a1, 0.f), part);
        }
        part += __shfl_xor_sync(~0u, part, 1);
        if (hf == 0) s_th[rl] = part + s_mlp[2700];
    }
    __syncthreads();

    // ---- first layer: t0 = sigma(x*au0x + th*au0t + b0), packed A-fragment layout ----
    float4* a4 = (float4*)dyn + w * 512;
    {
        const int rl = w * 16 + g;
        const float xa = s_x[rl], xb = s_x[rl + 8];
        const float ta = s_th[rl], tb = s_th[rl + 8];
#pragma unroll
        for (int ks = 0; ks < 16; ks++) {
            const int k1 = ks * 8 + c, k2 = k1 + 4;
            const float i00 = fmaf(xa, s_c[k1], fmaf(ta, s_c[128 + k1], s_c[256 + k1]));
            const float i10 = fmaf(xb, s_c[k1], fmaf(tb, s_c[128 + k1], s_c[256 + k1]));
            const float i01 = fmaf(xa, s_c[k2], fmaf(ta, s_c[128 + k2], s_c[256 + k2]));
            const float i11 = fmaf(xb, s_c[k2], fmaf(tb, s_c[128 + k2], s_c[256 + k2]));
            float4 v;
            v.x = __uint_as_float(f2tf32(sigmoid_fast(i00)));
            v.y = __uint_as_float(f2tf32(sigmoid_fast(i10)));
            v.z = __uint_as_float(f2tf32(sigmoid_fast(i01)));
            v.w = __uint_as_float(f2tf32(sigmoid_fast(i11)));
            a4[ks * 32 + lane] = v;
        }
    }

    // ---- 6 GEMM stages ----
#pragma unroll 1
    for (int s = 0; s < NSTAGE; s++) {
        MBARRIER_WAIT_PARITY((s & 1) ? mbW1 : mbW0, (s >> 1) & 1);
        float Cacc[16][4];
#pragma unroll
        for (int t = 0; t < 16; t++) { Cacc[t][0] = Cacc[t][1] = Cacc[t][2] = Cacc[t][3] = 0.f; }

        const float4* wb4 = (const float4*)(dyn + 16384 + (s & 1) * 16384);
#pragma unroll 1
        for (int kp = 0; kp < 8; kp++) {
            const float4 af0 = a4[(kp * 2 + 0) * 32 + lane];
            const float4 af1 = a4[(kp * 2 + 1) * 32 + lane];
            const uint32_t A0[4] = {__float_as_uint(af0.x), __float_as_uint(af0.y),
                                    __float_as_uint(af0.z), __float_as_uint(af0.w)};
            const uint32_t A1[4] = {__float_as_uint(af1.x), __float_as_uint(af1.y),
                                    __float_as_uint(af1.z), __float_as_uint(af1.w)};
#pragma unroll
            for (int t = 0; t < 16; t++) {
                const float4 bf = wb4[(t * 8 + kp) * 32 + lane];
                mma8(Cacc[t], A0, __float_as_uint(bf.x), __float_as_uint(bf.y));
                mma8(Cacc[t], A1, __float_as_uint(bf.z), __float_as_uint(bf.w));
            }
        }
        __syncthreads();  // all warps done reading wbuf(s&1)
        if (tid == 0 && s < NSTAGE - 2) {
            const uint32_t mb = (s & 1) ? mbW1 : mbW0;
            MBARRIER_EXPECT_TX(mb, 65536);
            BULK_G2S(dynb + 65536u + (uint32_t)(s & 1) * 65536u, &d_Gimg[s + 2][0], 65536, mb);
        }

        if (s < NSTAGE - 1) {
            const float* bias = s_c + 384 + s * 128;
            float* actf = dyn + w * 2048;
#pragma unroll
            for (int t = 0; t < 16; t++) {
                const int n0 = 8 * t + 2 * c;
                const float bi0 = bias[n0], bi1 = bias[n0 + 1];
                const float v00 = __uint_as_float(f2tf32(sigmoid_fast(Cacc[t][0] + bi0)));
                const float v01 = __uint_as_float(f2tf32(sigmoid_fast(Cacc[t][1] + bi1)));
                const float v10 = __uint_as_float(f2tf32(sigmoid_fast(Cacc[t][2] + bi0)));
                const float v11 = __uint_as_float(f2tf32(sigmoid_fast(Cacc[t][3] + bi1)));
                const int slot = t * 32 + 4 * g + ((2 * c) & 3);
                const int fi = slot * 4 + ((c >> 1) & 1) * 2;
                *(float2*)(actf + fi) = make_float2(v00, v10);
                *(float2*)(actf + fi + 4) = make_float2(v01, v11);
            }
            __syncwarp();
        } else {
            // final: t6 = sigma(C + bM5); out = sigma(t6 . v + bL)
            const float* bias = s_c + 384 + 5 * 128;
            float p0 = 0.f, p1 = 0.f;
#pragma unroll
            for (int t = 0; t < 16; t++) {
                const int n0 = 8 * t + 2 * c;
                const float bi0 = bias[n0], bi1 = bias[n0 + 1];
                const float vv0 = s_c[1152 + n0], vv1 = s_c[1152 + n0 + 1];
                p0 = fmaf(sigmoid_fast(Cacc[t][0] + bi0), vv0, p0);
                p0 = fmaf(sigmoid_fast(Cacc[t][1] + bi1), vv1, p0);
                p1 = fmaf(sigmoid_fast(Cacc[t][2] + bi0), vv0, p1);
                p1 = fmaf(sigmoid_fast(Cacc[t][3] + bi1), vv1, p1);
            }
            p0 += __shfl_xor_sync(~0u, p0, 1); p0 += __shfl_xor_sync(~0u, p0, 2);
            p1 += __shfl_xor_sync(~0u, p1, 1); p1 += __shfl_xor_sync(~0u, p1, 2);
            if (c == 0) {
                const int R = blockIdx.x * 128 + w * 16 + g;
                if (R < n) {
                    const float z0 = p0 + s_c[1280];
                    out[R] = __fdividef(1.0f, 1.0f + __expf(-z0));
                }
                if (R + 8 < n) {
                    const float z1 = p1 + s_c[1280];
                    out[R + 8] = __fdividef(1.0f, 1.0f + __expf(-z1));
                }
            }
        }
    }
}

// ===================== launch =====================
extern "C" void kernel_launch(void* const* d_in, const int* in_sizes, int n_in,
                              void* d_out, int out_size) {
    const float* x   = (const float*)d_in[0];
    const float* fy0 = (const float*)d_in[1];
    const float* u0  = (const float*)d_in[2];
    const float* w0  = (const float*)d_in[3];
    const float* la0 = (const float*)d_in[4];
    const float* b0  = (const float*)d_in[5];
    const float* uM  = (const float*)d_in[6];
    const float* wM  = (const float*)d_in[7];
    const float* laM = (const float*)d_in[8];
    const float* bM  = (const float*)d_in[9];
    const float* uL  = (const float*)d_in[10];
    // d_in[11] = wL: softmax of a [1,1] row == 1.0 (identity)
    const float* laL = (const float*)d_in[12];
    const float* bL  = (const float*)d_in[13];
    const float* W1  = (const float*)d_in[14];
    const float* b1  = (const float*)d_in[15];
    const float* W2  = (const float*)d_in[16];
    const float* b2  = (const float*)d_in[17];
    const float* W3  = (const float*)d_in[18];
    const float* b3  = (const float*)d_in[19];
    float* out = (float*)d_out;
    const int n = in_sizes[0];

    const int prep2_smem = (16384 + 2048) * 4;  // 73728
    const int fused_smem = 49152 * 4;           // 196608
    cudaFuncSetAttribute(prep2_kernel, cudaFuncAttributeMaxDynamicSharedMemorySize, prep2_smem);
    cudaFuncSetAttribute(fused_kernel, cudaFuncAttributeMaxDynamicSharedMemorySize, fused_smem);

    prep1_kernel<<<417, 128>>>(u0, w0, la0, b0, uM, wM, laM, bM, uL, laL, bL);
    prep2_kernel<<<49, 256, prep2_smem>>>();
    fused_kernel<<<(n + 127) / 128, 256, fused_smem>>>(x, fy0, W1, b1, W2, b2, W3, b3, out, n);
}

// round 7
// speedup vs baseline: 5.1658x; 1.1864x over previous
#include <cuda_runtime.h>
#include <math.h>
#include <stdint.h>

#define D 128
#define NSTAGE 6

// ===================== device globals =====================
__device__ __align__(16) float d_AUMf[6][D * D];       // exp(la)*softmax(uM), [o][j]
__device__ __align__(16) float d_Wf[7][D * D];         // softmax rows: [0]=w0, [1..6]=wM
__device__ __align__(128) float d_Gimg[NSTAGE][D * D]; // G_m tf32, B-fragment-packed (R5 layout)
__device__ float d_au0x[D], d_au0t[D], d_b0v[D];
__device__ float d_bMv[6][D];
__device__ float d_auLv[D];
__device__ float d_vfin[D];
__device__ float d_bLv;

// ===================== helpers =====================
__device__ __forceinline__ uint32_t smem_u32(const void* p) {
    uint32_t a;
    asm("{ .reg .u64 t; cvta.to.shared.u64 t, %1; cvt.u32.u64 %0, t; }" : "=r"(a) : "l"(p));
    return a;
}
__device__ __forceinline__ uint32_t f2tf32(float x) {
    uint32_t u; asm("cvt.rna.tf32.f32 %0, %1;" : "=r"(u) : "f"(x)); return u;
}
__device__ __forceinline__ float tanh_ap(float x) {
    float y; asm("tanh.approx.f32 %0, %1;" : "=f"(y) : "f"(x)); return y;
}
__device__ __forceinline__ float sigmoid_fast(float x) {
    return fmaf(tanh_ap(0.5f * x), 0.5f, 0.5f);
}

#define MBARRIER_INIT(mbar, count) \
    asm volatile("mbarrier.init.shared.b64 [%0], %1;" :: "r"((uint32_t)(mbar)), "r"((uint32_t)(count)) : "memory")
#define MBARRIER_EXPECT_TX(mbar, bytes) \
    asm volatile("mbarrier.arrive.expect_tx.shared.b64 _, [%0], %1;" :: "r"((uint32_t)(mbar)), "r"((uint32_t)(bytes)) : "memory")
#define MBARRIER_WAIT_PARITY(mbar, parity) do { \
    uint32_t _m = (uint32_t)(mbar); uint32_t _p = (uint32_t)(parity); uint32_t _d; \
    asm volatile("{\n\t.reg .pred p;\n\t" \
        "mbarrier.try_wait.parity.acquire.cta.shared::cta.b64 p, [%1], %2;\n\t" \
        "selp.b32 %0, 1, 0, p;\n\t}" : "=r"(_d) : "r"(_m), "r"(_p) : "memory"); \
    if (!_d) { \
        asm volatile("{\n\t.reg .pred P1;\n\t" \
            "WAIT_LOOP_%=:\n\t" \
            "mbarrier.try_wait.parity.acquire.cta.shared::cta.b64 P1, [%0], %1, 0x989680;\n\t" \
            "@P1 bra.uni WAIT_DONE_%=;\n\t" \
            "bra.uni WAIT_LOOP_%=;\n\t" \
            "WAIT_DONE_%=:\n\t}" :: "r"(_m), "r"(_p) : "memory"); \
    } \
} while (0)

#define BULK_G2S(smem, gptr, bytes, mbar) \
    asm volatile("cp.async.bulk.shared::cluster.global.mbarrier::complete_tx::bytes [%0], [%1], %2, [%3];" \
        :: "r"((uint32_t)(smem)), "l"(gptr), "r"((uint32_t)(bytes)), "r"((uint32_t)(mbar)) : "memory")

// mma.sync m16n8k8 tf32 (proven layout from R5; tcgen05 unavailable on plain sm_103 target)
__device__ __forceinline__ void mma8(float* d, const float4 a, float b0, float b1) {
    asm volatile(
        "mma.sync.aligned.m16n8k8.row.col.f32.tf32.tf32.f32 "
        "{%0,%1,%2,%3}, {%4,%5,%6,%7}, {%8,%9}, {%0,%1,%2,%3};"
        : "+f"(d[0]), "+f"(d[1]), "+f"(d[2]), "+f"(d[3])
        : "r"(__float_as_uint(a.x)), "r"(__float_as_uint(a.y)),
          "r"(__float_as_uint(a.z)), "r"(__float_as_uint(a.w)),
          "r"(__float_as_uint(b0)), "r"(__float_as_uint(b1)));
}

// ===================== prep1: warp-per-row softmax / folding =====================
__device__ __forceinline__ void warp_softmax_row(const float* __restrict__ row,
                                                 float* __restrict__ dst,
                                                 float scale, int lane) {
    float v[4];
#pragma unroll
    for (int q = 0; q < 4; q++) v[q] = row[lane + 32 * q];
    float m = fmaxf(fmaxf(v[0], v[1]), fmaxf(v[2], v[3]));
#pragma unroll
    for (int o = 16; o > 0; o >>= 1) m = fmaxf(m, __shfl_xor_sync(~0u, m, o));
    float e[4]; float s = 0.f;
#pragma unroll
    for (int q = 0; q < 4; q++) { e[q] = expf(v[q] - m); s += e[q]; }
#pragma unroll
    for (int o = 16; o > 0; o >>= 1) s += __shfl_xor_sync(~0u, s, o);
    const float inv = scale / s;
#pragma unroll
    for (int q = 0; q < 4; q++) dst[lane + 32 * q] = e[q] * inv;
}

__global__ void prep1_kernel(const float* __restrict__ u0, const float* __restrict__ w0,
                             const float* __restrict__ la0, const float* __restrict__ b0,
                             const float* __restrict__ uM, const float* __restrict__ wM,
                             const float* __restrict__ laM, const float* __restrict__ bM,
                             const float* __restrict__ uL, const float* __restrict__ laL,
                             const float* __restrict__ bL) {
    const int gw = (blockIdx.x * blockDim.x + threadIdx.x) >> 5;
    const int lane = threadIdx.x & 31;
    if (gw < 128) {
        warp_softmax_row(w0 + gw * D, d_Wf[0] + gw * D, 1.0f, lane);
    } else if (gw < 896) {
        const int m = (gw - 128) >> 7, o = (gw - 128) & 127;
        warp_softmax_row(uM + (m * D + o) * D, d_AUMf[m] + o * D, expf(laM[m * D + o]), lane);
        if (lane == 0) d_bMv[m][o] = bM[m * D + o];
    } else if (gw < 1664) {
        const int m = (gw - 896) >> 7, o = (gw - 896) & 127;
        warp_softmax_row(wM + (m * D + o) * D, d_Wf[1 + m] + o * D, 1.0f, lane);
    } else if (gw == 1664) {
#pragma unroll
        for (int q = 0; q < 4; q++) {
            const int o = lane + 32 * q;
            float v0 = u0[o * 2 + 0], v1 = u0[o * 2 + 1];
            float m = fmaxf(v0, v1);
            float e0 = expf(v0 - m), e1 = expf(v1 - m);
            float inv = expf(la0[o]) / (e0 + e1);
            d_au0x[o] = e0 * inv;
            d_au0t[o] = e1 * inv;
            d_b0v[o] = b0[o];
        }
    } else if (gw == 1665) {
        warp_softmax_row(uL, d_auLv, expf(laL[0]), lane);
        if (lane == 0) d_bLv = bL[0];
    }
}

// ===================== prep2: G_m = AUM[m] @ Wf[m] -> tf32, B-fragment pack (R5-proven) =====================
__global__ void prep2_kernel() {
    extern __shared__ float sh[];   // 16384 (W) + 2048 (AU rows)
    float* sW = sh;
    float* sAU = sh + 16384;
    const int b = blockIdx.x, tid = threadIdx.x;
    if (b < 48) {
        const int m = b >> 3;
        const int oc = (b & 7) * 16;
        for (int i = tid; i < 16384; i += 256) sW[i] = d_Wf[m][i];
        for (int i = tid; i < 2048; i += 256) sAU[i] = d_AUMf[m][oc * D + i];
        __syncthreads();
#pragma unroll 1
        for (int q = 0; q < 8; q++) {
            const int idx = tid + q * 256;
            const int ol = idx >> 7, i = idx & 127;
            const float* au = sAU + ol * D;
            float acc = 0.f;
#pragma unroll 8
            for (int j = 0; j < D; j++) acc = fmaf(au[j], sW[j * D + i], acc);
            const int o = oc + ol;
            // B-fragment pack for mma.sync m16n8k8 tf32: value G[n=o][k=i]
            const int t = o >> 3, g = o & 7;
            const int kp = i >> 4, ks1 = (i >> 3) & 1;
            const int c = i & 3, half = (i >> 2) & 1;
            const int flat = (((t * 8 + kp) * 32) + g * 4 + c) * 4 + ks1 * 2 + half;
            d_Gimg[m][flat] = __uint_as_float(f2tf32(acc));
        }
    } else {
        if (tid < D) {
            float acc = 0.f;
            for (int j = 0; j < D; j++) acc = fmaf(d_auLv[j], d_Wf[6][j * D + tid], acc);
            d_vfin[tid] = acc;
        }
    }
}

// ===================== fused kernel =====================
// 128 rows/CTA. Warp w=(wm=w>>1, wn=w&1): rows [wm*32,+32), cols [wn*64,+64).
// dyn (floats): [0,16384): Apack (CTA-shared A-fragments, tf32-in-fp32);
//               [16384,32768): wbuf0; [32768,49152): wbuf1.
// Apack layout: float4 slot ((mt*8+kp)*2+h)*32 + lane, mt=m-tile(16 rows), kp=k16-tile, h=k8 half.
__global__ void __launch_bounds__(256, 1) fused_kernel(
    const float* __restrict__ x, const float* __restrict__ fy0,
    const float* __restrict__ W1, const float* __restrict__ b1,
    const float* __restrict__ W2, const float* __restrict__ b2,
    const float* __restrict__ W3, const float* __restrict__ b3,
    float* __restrict__ out, int n) {
    extern __shared__ float dyn[];
    __shared__ float s_c[1281];     // au0x|au0t|b0|bM[6]|v|bL
    __shared__ float s_mlp[2701];   // W1|b1|b2|W3|W2|b3
    __shared__ float s_x[128], s_fy[128], s_th[128];
    __shared__ float s_fin[256];
    __shared__ __align__(8) unsigned long long s_bar[2];

    const int tid = threadIdx.x;
    const int w = tid >> 5, lane = tid & 31;
    const int g = lane >> 2, tig = lane & 3;
    const int wm = w >> 1, wn = w & 1;
    const uint32_t mbW0 = smem_u32(&s_bar[0]);
    const uint32_t mbW1 = smem_u32(&s_bar[1]);
    const uint32_t dynb = smem_u32(dyn);

    float4* a4 = (float4*)dyn;   // 4096 float4 = 64KB Apack
    if (tid == 0) {
        MBARRIER_INIT(mbW0, 1); MBARRIER_INIT(mbW1, 1);
        MBARRIER_EXPECT_TX(mbW0, 65536);
        BULK_G2S(dynb + 65536u, &d_Gimg[0][0], 65536, mbW0);
        MBARRIER_EXPECT_TX(mbW1, 65536);
        BULK_G2S(dynb + 131072u, &d_Gimg[1][0], 65536, mbW1);
        s_c[1280] = d_bLv;
        s_mlp[2700] = b3[0];
    }
    {
        const int gi = blockIdx.x * 128 + tid;
        if (tid < 128) {
            const bool ok = gi < n;
            s_x[tid] = ok ? x[gi] : 0.f;
            s_fy[tid] = ok ? fy0[gi] : 0.f;
            s_c[tid] = d_au0x[tid];
            s_c[128 + tid] = d_au0t[tid];
            s_c[256 + tid] = d_b0v[tid];
#pragma unroll
            for (int m = 0; m < 6; m++) s_c[384 + m * 128 + tid] = d_bMv[m][tid];
            s_c[1152 + tid] = d_vfin[tid];
        }
        if (tid < 50) {
            s_mlp[tid] = W1[tid]; s_mlp[50 + tid] = b1[tid];
            s_mlp[100 + tid] = b2[tid]; s_mlp[150 + tid] = W3[tid];
        }
        for (int i = tid; i < 2500; i += 256) s_mlp[200 + i] = W2[i];
    }
    __syncthreads();

    // ---- theta MLP: 2 threads per row ----
    {
        const int rl = tid >> 1, hf = tid & 1;
        const float fv = s_fy[rl];
        float h1[50];
#pragma unroll
        for (int j = 0; j < 50; j++) h1[j] = fmaxf(fmaf(s_mlp[j], fv, s_mlp[50 + j]), 0.f);
        float part = 0.f;
        const int j0 = hf * 25;
#pragma unroll 1
        for (int j = j0; j < j0 + 25; j++) {
            const float* wr = s_mlp + 200 + j * 50;
            float a0 = s_mlp[100 + j], a1 = 0.f;
#pragma unroll
            for (int k = 0; k < 50; k += 2) { a0 = fmaf(wr[k], h1[k], a0); a1 = fmaf(wr[k + 1], h1[k + 1], a1); }
            part = fmaf(s_mlp[150 + j], fmaxf(a0 + a1, 0.f), part);
        }
        part += __shfl_xor_sync(~0u, part, 1);
        if (hf == 0) s_th[rl] = part + s_mlp[2700];
    }
    __syncthreads();

    // ---- first layer: t0 = sigma(x*au0x + th*au0t + b0) -> Apack (warp w owns m-tile w) ----
    {
        const int l0 = w * 16 + g, l1 = l0 + 8;
        const float x0 = s_x[l0], x1 = s_x[l1];
        const float t0v = s_th[l0], t1v = s_th[l1];
#pragma unroll
        for (int kp = 0; kp < 8; kp++) {
#pragma unroll
            for (int h = 0; h < 2; h++) {
                const int k1 = kp * 16 + h * 8 + tig;
                const int k2 = k1 + 4;
                float4 v;
                v.x = __uint_as_float(f2tf32(sigmoid_fast(fmaf(x0, s_c[k1], fmaf(t0v, s_c[128 + k1], s_c[256 + k1])))));
                v.y = __uint_as_float(f2tf32(sigmoid_fast(fmaf(x1, s_c[k1], fmaf(t1v, s_c[128 + k1], s_c[256 + k1])))));
                v.z = __uint_as_float(f2tf32(sigmoid_fast(fmaf(x0, s_c[k2], fmaf(t0v, s_c[128 + k2], s_c[256 + k2])))));
                v.w = __uint_as_float(f2tf32(sigmoid_fast(fmaf(x1, s_c[k2], fmaf(t1v, s_c[128 + k2], s_c[256 + k2])))));
                a4[((w * 8 + kp) * 2 + h) * 32 + lane] = v;
            }
        }
    }
    __syncthreads();

    const int mt0 = wm * 2, mt1 = mt0 + 1;

    // ---- 6 GEMM stages ----
#pragma unroll 1
    for (int s = 0; s < NSTAGE; s++) {
        MBARRIER_WAIT_PARITY((s & 1) ? mbW1 : mbW0, (s >> 1) & 1);

        float Cacc[2][8][4];
#pragma unroll
        for (int tm = 0; tm < 2; tm++)
#pragma unroll
            for (int t = 0; t < 8; t++) {
                Cacc[tm][t][0] = 0.f; Cacc[tm][t][1] = 0.f;
                Cacc[tm][t][2] = 0.f; Cacc[tm][t][3] = 0.f;
            }

        const float4* wb4 = (const float4*)(dyn + 16384 + (s & 1) * 16384);
#pragma unroll 1
        for (int kp = 0; kp < 8; kp++) {
            const float4 A00 = a4[((mt0 * 8 + kp) * 2 + 0) * 32 + lane];
            const float4 A01 = a4[((mt0 * 8 + kp) * 2 + 1) * 32 + lane];
            const float4 A10 = a4[((mt1 * 8 + kp) * 2 + 0) * 32 + lane];
            const float4 A11 = a4[((mt1 * 8 + kp) * 2 + 1) * 32 + lane];
#pragma unroll
            for (int tl = 0; tl < 8; tl++) {
                const float4 bf = wb4[(((wn * 8 + tl) * 8 + kp) * 32) + lane];
                mma8(Cacc[0][tl], A00, bf.x, bf.y);
                mma8(Cacc[0][tl], A01, bf.z, bf.w);
                mma8(Cacc[1][tl], A10, bf.x, bf.y);
                mma8(Cacc[1][tl], A11, bf.z, bf.w);
            }
        }
        __syncthreads();   // all warps done reading wbuf(s&1) + Apack
        if (tid == 0 && s < NSTAGE - 2) {
            const uint32_t mb = (s & 1) ? mbW1 : mbW0;
            MBARRIER_EXPECT_TX(mb, 65536);
            BULK_G2S(dynb + 65536u + (uint32_t)(s & 1) * 65536u, &d_Gimg[s + 2][0], 65536, mb);
        }

        if (s < NSTAGE - 1) {
            const float* bias = s_c + 384 + s * 128;
            float* actf = dyn;
#pragma unroll
            for (int tm = 0; tm < 2; tm++) {
                const int mt = mt0 + tm;
#pragma unroll
                for (int tl = 0; tl < 8; tl++) {
                    const int tg = wn * 8 + tl;        // global 8-col tile = k8 group
                    const int n0 = tg * 8 + 2 * tig;
                    const float b0v = bias[n0], b1v = bias[n0 + 1];
                    const float v00 = __uint_as_float(f2tf32(sigmoid_fast(Cacc[tm][tl][0] + b0v)));
                    const float v01 = __uint_as_float(f2tf32(sigmoid_fast(Cacc[tm][tl][1] + b1v)));
                    const float v10 = __uint_as_float(f2tf32(sigmoid_fast(Cacc[tm][tl][2] + b0v)));
                    const float v11 = __uint_as_float(f2tf32(sigmoid_fast(Cacc[tm][tl][3] + b1v)));
                    const int kp = tg >> 1, h = tg & 1;
                    const int slot = ((mt * 8 + kp) * 2 + h) * 32 + 4 * g + ((2 * tig) & 3);
                    const int fi = slot * 4 + ((tig >> 1) & 1) * 2;
                    *(float2*)(actf + fi) = make_float2(v00, v10);
                    *(float2*)(actf + fi + 4) = make_float2(v01, v11);
                }
            }
            __syncthreads();   // Apack ready for next stage
        } else {
            // final: t6 = sigma(C + bM5); partial dot with v; cross-wn reduce via s_fin
            const float* bias = s_c + 384 + 5 * 128;
            float p[2][2];
            p[0][0] = p[0][1] = p[1][0] = p[1][1] = 0.f;
#pragma unroll
            for (int tm = 0; tm < 2; tm++)
#pragma unroll
                for (int t = 0; t < 8; t++) {
                    const int n0 = wn * 64 + t * 8 + 2 * tig;
                    const float b0v = bias[n0], b1v = bias[n0 + 1];
                    const float v0 = s_c[1152 + n0], v1 = s_c[1152 + n0 + 1];
                    p[tm][0] = fmaf(sigmoid_fast(Cacc[tm][t][0] + b0v), v0, p[tm][0]);
                    p[tm][0] = fmaf(sigmoid_fast(Cacc[tm][t][1] + b1v), v1, p[tm][0]);
                    p[tm][1] = fmaf(sigmoid_fast(Cacc[tm][t][2] + b0v), v0, p[tm][1]);
                    p[tm][1] = fmaf(sigmoid_fast(Cacc[tm][t][3] + b1v), v1, p[tm][1]);
                }
#pragma unroll
            for (int tm = 0; tm < 2; tm++) {
#pragma unroll
                for (int rr = 0; rr < 2; rr++) {
                    p[tm][rr] += __shfl_xor_sync(~0u, p[tm][rr], 1);
                    p[tm][rr] += __shfl_xor_sync(~0u, p[tm][rr], 2);
                }
                if (tig == 0) {
                    const int lr = wm * 32 + tm * 16 + g;
                    s_fin[wn * 128 + lr] = p[tm][0];
                    s_fin[wn * 128 + lr + 8] = p[tm][1];
                }
            }
            __syncthreads();
            if (tid < 128) {
                const int R = blockIdx.x * 128 + tid;
                if (R < n) {
                    const float z = s_fin[tid] + s_fin[128 + tid] + s_c[1280];
                    out[R] = __fdividef(1.0f, 1.0f + __expf(-z));
                }
            }
        }
    }
}

// ===================== launch =====================
extern "C" void kernel_launch(void* const* d_in, const int* in_sizes, int n_in,
                              void* d_out, int out_size) {
    const float* x   = (const float*)d_in[0];
    const float* fy0 = (const float*)d_in[1];
    const float* u0  = (const float*)d_in[2];
    const float* w0  = (const float*)d_in[3];
    const float* la0 = (const float*)d_in[4];
    const float* b0  = (const float*)d_in[5];
    const float* uM  = (const float*)d_in[6];
    const float* wM  = (const float*)d_in[7];
    const float* laM = (const float*)d_in[8];
    const float* bM  = (const float*)d_in[9];
    const float* uL  = (const float*)d_in[10];
    // d_in[11] = wL: softmax of a [1,1] row == 1.0 (identity)
    const float* laL = (const float*)d_in[12];
    const float* bL  = (const float*)d_in[13];
    const float* W1  = (const float*)d_in[14];
    const float* b1  = (const float*)d_in[15];
    const float* W2  = (const float*)d_in[16];
    const float* b2  = (const float*)d_in[17];
    const float* W3  = (const float*)d_in[18];
    const float* b3  = (const float*)d_in[19];
    float* out = (float*)d_out;
    const int n = in_sizes[0];

    const int prep2_smem = (16384 + 2048) * 4;  // 73728
    const int fused_smem = 49152 * 4;           // 196608: 64KB Apack + 2x64KB wbuf
    cudaFuncSetAttribute(prep2_kernel, cudaFuncAttributeMaxDynamicSharedMemorySize, prep2_smem);
    cudaFuncSetAttribute(fused_kernel, cudaFuncAttributeMaxDynamicSharedMemorySize, fused_smem);

    prep1_kernel<<<417, 128>>>(u0, w0, la0, b0, uM, wM, laM, bM, uL, laL, bL);
    prep2_kernel<<<49, 256, prep2_smem>>>();
    fused_kernel<<<(n + 127) / 128, 256, fused_smem>>>(x, fy0, W1, b1, W2, b2, W3, b3, out, n);
}

// round 8
// speedup vs baseline: 9.8739x; 1.9114x over previous
#include <cuda_runtime.h>
#include <cuda_fp16.h>
#include <math.h>
#include <stdint.h>

#define D 128
#define NSTAGE 6

// ===================== device globals =====================
__device__ __align__(16) float d_AUMf[6][D * D];         // exp(la)*softmax(uM), [o][j]
__device__ __align__(16) float d_Wf[7][D * D];           // softmax rows: [0]=w0, [1..6]=wM
__device__ __align__(128) __half d_Gpack[NSTAGE][D * D]; // G_m fp16, B-fragment-packed
__device__ float d_au0x[D], d_au0t[D], d_b0v[D];
__device__ float d_bMv[6][D];
__device__ float d_auLv[D];
__device__ float d_vfin[D];
__device__ float d_bLv;

// ===================== helpers =====================
__device__ __forceinline__ uint32_t smem_u32(const void* p) {
    uint32_t a;
    asm("{ .reg .u64 t; cvta.to.shared.u64 t, %1; cvt.u32.u64 %0, t; }" : "=r"(a) : "l"(p));
    return a;
}
__device__ __forceinline__ float tanh_ap(float x) {
    float y; asm("tanh.approx.f32 %0, %1;" : "=f"(y) : "f"(x)); return y;
}
__device__ __forceinline__ float sigmoid_fast(float x) {
    return fmaf(tanh_ap(0.5f * x), 0.5f, 0.5f);
}
__device__ __forceinline__ float pk2(float lo, float hi) {   // half2{lo,hi} bit-cast to float
    __half2 h = __floats2half2_rn(lo, hi);
    return __uint_as_float(*(uint32_t*)&h);
}

#define MBARRIER_INIT(mbar, count) \
    asm volatile("mbarrier.init.shared.b64 [%0], %1;" :: "r"((uint32_t)(mbar)), "r"((uint32_t)(count)) : "memory")
#define MBARRIER_EXPECT_TX(mbar, bytes) \
    asm volatile("mbarrier.arrive.expect_tx.shared.b64 _, [%0], %1;" :: "r"((uint32_t)(mbar)), "r"((uint32_t)(bytes)) : "memory")
#define MBARRIER_WAIT_PARITY(mbar, parity) do { \
    uint32_t _m = (uint32_t)(mbar); uint32_t _p = (uint32_t)(parity); uint32_t _d; \
    asm volatile("{\n\t.reg .pred p;\n\t" \
        "mbarrier.try_wait.parity.acquire.cta.shared::cta.b64 p, [%1], %2;\n\t" \
        "selp.b32 %0, 1, 0, p;\n\t}" : "=r"(_d) : "r"(_m), "r"(_p) : "memory"); \
    if (!_d) { \
        asm volatile("{\n\t.reg .pred P1;\n\t" \
            "WAIT_LOOP_%=:\n\t" \
            "mbarrier.try_wait.parity.acquire.cta.shared::cta.b64 P1, [%0], %1, 0x989680;\n\t" \
            "@P1 bra.uni WAIT_DONE_%=;\n\t" \
            "bra.uni WAIT_LOOP_%=;\n\t" \
            "WAIT_DONE_%=:\n\t}" :: "r"(_m), "r"(_p) : "memory"); \
    } \
} while (0)

#define BULK_G2S(smem, gptr, bytes, mbar) \
    asm volatile("cp.async.bulk.shared::cluster.global.mbarrier::complete_tx::bytes [%0], [%1], %2, [%3];" \
        :: "r"((uint32_t)(smem)), "l"(gptr), "r"((uint32_t)(bytes)), "r"((uint32_t)(mbar)) : "memory")

// mma.sync m16n8k16 fp16 -> fp32 accum
__device__ __forceinline__ void mma16(float* d, const float4 a, float b0, float b1) {
    asm volatile(
        "mma.sync.aligned.m16n8k16.row.col.f32.f16.f16.f32 "
        "{%0,%1,%2,%3}, {%4,%5,%6,%7}, {%8,%9}, {%0,%1,%2,%3};"
        : "+f"(d[0]), "+f"(d[1]), "+f"(d[2]), "+f"(d[3])
        : "r"(__float_as_uint(a.x)), "r"(__float_as_uint(a.y)),
          "r"(__float_as_uint(a.z)), "r"(__float_as_uint(a.w)),
          "r"(__float_as_uint(b0)), "r"(__float_as_uint(b1)));
}

// ===================== prep1: warp-per-row softmax / folding =====================
__device__ __forceinline__ void warp_softmax_row(const float* __restrict__ row,
                                                 float* __restrict__ dst,
                                                 float scale, int lane) {
    float v[4];
#pragma unroll
    for (int q = 0; q < 4; q++) v[q] = row[lane + 32 * q];
    float m = fmaxf(fmaxf(v[0], v[1]), fmaxf(v[2], v[3]));
#pragma unroll
    for (int o = 16; o > 0; o >>= 1) m = fmaxf(m, __shfl_xor_sync(~0u, m, o));
    float e[4]; float s = 0.f;
#pragma unroll
    for (int q = 0; q < 4; q++) { e[q] = expf(v[q] - m); s += e[q]; }
#pragma unroll
    for (int o = 16; o > 0; o >>= 1) s += __shfl_xor_sync(~0u, s, o);
    const float inv = scale / s;
#pragma unroll
    for (int q = 0; q < 4; q++) dst[lane + 32 * q] = e[q] * inv;
}

__global__ void prep1_kernel(const float* __restrict__ u0, const float* __restrict__ w0,
                             const float* __restrict__ la0, const float* __restrict__ b0,
                             const float* __restrict__ uM, const float* __restrict__ wM,
                             const float* __restrict__ laM, const float* __restrict__ bM,
                             const float* __restrict__ uL, const float* __restrict__ laL,
                             const float* __restrict__ bL) {
    const int gw = (blockIdx.x * blockDim.x + threadIdx.x) >> 5;
    const int lane = threadIdx.x & 31;
    if (gw < 128) {
        warp_softmax_row(w0 + gw * D, d_Wf[0] + gw * D, 1.0f, lane);
    } else if (gw < 896) {
        const int m = (gw - 128) >> 7, o = (gw - 128) & 127;
        warp_softmax_row(uM + (m * D + o) * D, d_AUMf[m] + o * D, expf(laM[m * D + o]), lane);
        if (lane == 0) d_bMv[m][o] = bM[m * D + o];
    } else if (gw < 1664) {
        const int m = (gw - 896) >> 7, o = (gw - 896) & 127;
        warp_softmax_row(wM + (m * D + o) * D, d_Wf[1 + m] + o * D, 1.0f, lane);
    } else if (gw == 1664) {
#pragma unroll
        for (int q = 0; q < 4; q++) {
            const int o = lane + 32 * q;
            float v0 = u0[o * 2 + 0], v1 = u0[o * 2 + 1];
            float m = fmaxf(v0, v1);
            float e0 = expf(v0 - m), e1 = expf(v1 - m);
            float inv = expf(la0[o]) / (e0 + e1);
            d_au0x[o] = e0 * inv;
            d_au0t[o] = e1 * inv;
            d_b0v[o] = b0[o];
        }
    } else if (gw == 1665) {
        warp_softmax_row(uL, d_auLv, expf(laL[0]), lane);
        if (lane == 0) d_bLv = bL[0];
    }
}

// ===================== prep2: G_m = AUM[m] @ Wf[m] -> fp16 B-fragment pack; v =====================
__global__ void prep2_kernel() {
    extern __shared__ float sh[];   // 16384 (W) + 2048 (AU rows)
    float* sW = sh;
    float* sAU = sh + 16384;
    const int b = blockIdx.x, tid = threadIdx.x;
    if (b < 48) {
        const int m = b >> 3;
        const int oc = (b & 7) * 16;
        for (int i = tid; i < 16384; i += 256) sW[i] = d_Wf[m][i];
        for (int i = tid; i < 2048; i += 256) sAU[i] = d_AUMf[m][oc * D + i];
        __syncthreads();
#pragma unroll 1
        for (int q = 0; q < 8; q++) {
            const int idx = tid + q * 256;
            const int ol = idx >> 7, i = idx & 127;
            const float* au = sAU + ol * D;
            float acc = 0.f;
#pragma unroll 8
            for (int j = 0; j < D; j++) acc = fmaf(au[j], sW[j * D + i], acc);
            const int o = oc + ol;
            // B-fragment pack for mma m16n8k16 f16: value G[n=o][k=i]
            // b0 halfs = k rows 2c+{0,1} col g ; b1 halfs = k rows 8+2c+{0,1}
            const int t = o >> 3, g = o & 7;
            const int kp = i >> 4, o16 = i & 15;
            const int breg = o16 >> 3, tg = (o16 >> 1) & 3, hl = i & 1;
            const int hidx = ((((t * 8 + kp) * 32 + g * 4 + tg) * 2 + breg) << 1) | hl;
            d_Gpack[m][hidx] = __float2half_rn(acc);
        }
    } else {
        if (tid < D) {
            float acc = 0.f;
            for (int j = 0; j < D; j++) acc = fmaf(d_auLv[j], d_Wf[6][j * D + tid], acc);
            d_vfin[tid] = acc;
        }
    }
}

// ===================== fused kernel =====================
// 128 rows/CTA. Warp w=(wm=w>>1, wn=w&1): rows [wm*32,+32), cols [wn*64,+64).
// dyn (floats): [0,8192): Apack fp16 A-fragments (32KB, 2048 float4 slots);
//               [8192,16384): wbuf0 (32KB); [16384,24576): wbuf1 (32KB).
// Apack slot (mt*8+kp)*32+lane holds float4{a0,a1,a2,a3} (packed half2 each) for
// m-tile mt (16 rows), k16-tile kp. MLP weights borrow Apack region pre-stage-0.
__global__ void __launch_bounds__(256, 2) fused_kernel(
    const float* __restrict__ x, const float* __restrict__ fy0,
    const float* __restrict__ W1, const float* __restrict__ b1,
    const float* __restrict__ W2, const float* __restrict__ b2,
    const float* __restrict__ W3, const float* __restrict__ b3,
    float* __restrict__ out, int n) {
    extern __shared__ float dyn[];
    __shared__ float s_c[1281];     // au0x|au0t|b0|bM[6]|v|bL
    __shared__ float s_x[128], s_fy[128], s_th[128];
    __shared__ float s_fin[256];
    __shared__ __align__(8) unsigned long long s_bar[2];

    const int tid = threadIdx.x;
    const int w = tid >> 5, lane = tid & 31;
    const int g = lane >> 2, tig = lane & 3;
    const int wm = w >> 1, wn = w & 1;
    const uint32_t mbW0 = smem_u32(&s_bar[0]);
    const uint32_t mbW1 = smem_u32(&s_bar[1]);
    const uint32_t dynb = smem_u32(dyn);

    float4* a4 = (float4*)dyn;      // 2048 float4 = 32KB Apack
    float* s_mlp = dyn;             // MLP weights borrow Apack region before stage 0

    if (tid == 0) {
        MBARRIER_INIT(mbW0, 1); MBARRIER_INIT(mbW1, 1);
        MBARRIER_EXPECT_TX(mbW0, 32768);
        BULK_G2S(dynb + 32768u, &d_Gpack[0][0], 32768, mbW0);
        MBARRIER_EXPECT_TX(mbW1, 32768);
        BULK_G2S(dynb + 65536u, &d_Gpack[1][0], 32768, mbW1);
        s_c[1280] = d_bLv;
    }
    {
        const int gi = blockIdx.x * 128 + tid;
        if (tid < 128) {
            const bool ok = gi < n;
            s_x[tid] = ok ? x[gi] : 0.f;
            s_fy[tid] = ok ? fy0[gi] : 0.f;
            s_c[tid] = d_au0x[tid];
            s_c[128 + tid] = d_au0t[tid];
            s_c[256 + tid] = d_b0v[tid];
#pragma unroll
            for (int m = 0; m < 6; m++) s_c[384 + m * 128 + tid] = d_bMv[m][tid];
            s_c[1152 + tid] = d_vfin[tid];
        }
        if (tid < 50) {
            s_mlp[tid] = W1[tid]; s_mlp[50 + tid] = b1[tid];
            s_mlp[100 + tid] = b2[tid]; s_mlp[150 + tid] = W3[tid];
        }
        if (tid == 0) s_mlp[2700] = b3[0];
        for (int i = tid; i < 2500; i += 256) s_mlp[200 + i] = W2[i];
    }
    __syncthreads();

    // ---- theta MLP: 2 threads per row (weights in Apack region) ----
    {
        const int rl = tid >> 1, hf = tid & 1;
        const float fv = s_fy[rl];
        float h1[50];
#pragma unroll
        for (int j = 0; j < 50; j++) h1[j] = fmaxf(fmaf(s_mlp[j], fv, s_mlp[50 + j]), 0.f);
        float part = 0.f;
        const int j0 = hf * 25;
#pragma unroll 1
        for (int j = j0; j < j0 + 25; j++) {
            const float* wr = s_mlp + 200 + j * 50;
            float a0 = s_mlp[100 + j], a1 = 0.f;
#pragma unroll
            for (int k = 0; k < 50; k += 2) { a0 = fmaf(wr[k], h1[k], a0); a1 = fmaf(wr[k + 1], h1[k + 1], a1); }
            part = fmaf(s_mlp[150 + j], fmaxf(a0 + a1, 0.f), part);
        }
        part += __shfl_xor_sync(~0u, part, 1);
        if (hf == 0) s_th[rl] = part + s_mlp[2700];
    }
    __syncthreads();   // theta done; Apack region free for A-fragments

    // ---- first layer: t0 = sigma(x*au0x + th*au0t + b0) -> Apack (warp w owns m-tile w) ----
    {
        const int l0 = w * 16 + g, l1 = l0 + 8;
        const float x0 = s_x[l0], x1 = s_x[l1];
        const float t0v = s_th[l0], t1v = s_th[l1];
#pragma unroll
        for (int kp = 0; kp < 8; kp++) {
            const int k0 = kp * 16 + 2 * tig;
            const int k8 = k0 + 8;
            float4 v;
            v.x = pk2(sigmoid_fast(fmaf(x0, s_c[k0], fmaf(t0v, s_c[128 + k0], s_c[256 + k0]))),
                      sigmoid_fast(fmaf(x0, s_c[k0 + 1], fmaf(t0v, s_c[128 + k0 + 1], s_c[256 + k0 + 1]))));
            v.y = pk2(sigmoid_fast(fmaf(x1, s_c[k0], fmaf(t1v, s_c[128 + k0], s_c[256 + k0]))),
                      sigmoid_fast(fmaf(x1, s_c[k0 + 1], fmaf(t1v, s_c[128 + k0 + 1], s_c[256 + k0 + 1]))));
            v.z = pk2(sigmoid_fast(fmaf(x0, s_c[k8], fmaf(t0v, s_c[128 + k8], s_c[256 + k8]))),
                      sigmoid_fast(fmaf(x0, s_c[k8 + 1], fmaf(t0v, s_c[128 + k8 + 1], s_c[256 + k8 + 1]))));
            v.w = pk2(sigmoid_fast(fmaf(x1, s_c[k8], fmaf(t1v, s_c[128 + k8], s_c[256 + k8]))),
                      sigmoid_fast(fmaf(x1, s_c[k8 + 1], fmaf(t1v, s_c[128 + k8 + 1], s_c[256 + k8 + 1]))));
            a4[(w * 8 + kp) * 32 + lane] = v;
        }
    }
    __syncthreads();

    const int mt0 = wm * 2, mt1 = mt0 + 1;

    // ---- 6 GEMM stages ----
#pragma unroll 1
    for (int s = 0; s < NSTAGE; s++) {
        MBARRIER_WAIT_PARITY((s & 1) ? mbW1 : mbW0, (s >> 1) & 1);

        float Cacc[2][8][4];
#pragma unroll
        for (int tm = 0; tm < 2; tm++)
#pragma unroll
            for (int t = 0; t < 8; t++) {
                Cacc[tm][t][0] = 0.f; Cacc[tm][t][1] = 0.f;
                Cacc[tm][t][2] = 0.f; Cacc[tm][t][3] = 0.f;
            }

        const float2* wb2 = (const float2*)(dyn + 8192 + (s & 1) * 8192);
#pragma unroll 1
        for (int kp = 0; kp < 8; kp++) {
            const float4 A0 = a4[(mt0 * 8 + kp) * 32 + lane];
            const float4 A1 = a4[(mt1 * 8 + kp) * 32 + lane];
#pragma unroll
            for (int tl = 0; tl < 8; tl++) {
                const float2 bf = wb2[(((wn * 8 + tl) * 8 + kp) * 32) + lane];
                mma16(Cacc[0][tl], A0, bf.x, bf.y);
                mma16(Cacc[1][tl], A1, bf.x, bf.y);
            }
        }
        __syncthreads();   // all warps done reading wbuf(s&1) + Apack
        if (tid == 0 && s < NSTAGE - 2) {
            const uint32_t mb = (s & 1) ? mbW1 : mbW0;
            MBARRIER_EXPECT_TX(mb, 32768);
            BULK_G2S(dynb + 32768u + (uint32_t)(s & 1) * 32768u, &d_Gpack[s + 2][0], 32768, mb);
        }

        if (s < NSTAGE - 1) {
            const float* bias = s_c + 384 + s * 128;
#pragma unroll
            for (int tm = 0; tm < 2; tm++) {
                const int mt = mt0 + tm;
#pragma unroll
                for (int q = 0; q < 4; q++) {
                    const int kp = wn * 4 + q;
                    const int n0 = kp * 16 + 2 * tig;   // tl=2q cols (h=0)
                    const int n1 = n0 + 8;              // tl=2q+1 cols (h=1)
                    const float b00 = bias[n0], b01 = bias[n0 + 1];
                    const float b10 = bias[n1], b11 = bias[n1 + 1];
                    float4 v;
                    v.x = pk2(sigmoid_fast(Cacc[tm][2 * q][0] + b00),
                              sigmoid_fast(Cacc[tm][2 * q][1] + b01));
                    v.y = pk2(sigmoid_fast(Cacc[tm][2 * q][2] + b00),
                              sigmoid_fast(Cacc[tm][2 * q][3] + b01));
                    v.z = pk2(sigmoid_fast(Cacc[tm][2 * q + 1][0] + b10),
                              sigmoid_fast(Cacc[tm][2 * q + 1][1] + b11));
                    v.w = pk2(sigmoid_fast(Cacc[tm][2 * q + 1][2] + b10),
                              sigmoid_fast(Cacc[tm][2 * q + 1][3] + b11));
                    a4[(mt * 8 + kp) * 32 + lane] = v;
                }
            }
            __syncthreads();   // Apack ready for next stage
        } else {
            // final: t6 = sigma(C + bM5); partial dot with v; cross-wn reduce via s_fin
            const float* bias = s_c + 384 + 5 * 128;
            float p[2][2];
            p[0][0] = p[0][1] = p[1][0] = p[1][1] = 0.f;
#pragma unroll
            for (int tm = 0; tm < 2; tm++)
#pragma unroll
                for (int t = 0; t < 8; t++) {
                    const int n0 = wn * 64 + t * 8 + 2 * tig;
                    const float b0v = bias[n0], b1v = bias[n0 + 1];
                    const float v0 = s_c[1152 + n0], v1 = s_c[1152 + n0 + 1];
                    p[tm][0] = fmaf(sigmoid_fast(Cacc[tm][t][0] + b0v), v0, p[tm][0]);
                    p[tm][0] = fmaf(sigmoid_fast(Cacc[tm][t][1] + b1v), v1, p[tm][0]);
                    p[tm][1] = fmaf(sigmoid_fast(Cacc[tm][t][2] + b0v), v0, p[tm][1]);
                    p[tm][1] = fmaf(sigmoid_fast(Cacc[tm][t][3] + b1v), v1, p[tm][1]);
                }
#pragma unroll
            for (int tm = 0; tm < 2; tm++) {
#pragma unroll
                for (int rr = 0; rr < 2; rr++) {
                    p[tm][rr] += __shfl_xor_sync(~0u, p[tm][rr], 1);
                    p[tm][rr] += __shfl_xor_sync(~0u, p[tm][rr], 2);
                }
                if (tig == 0) {
                    const int lr = wm * 32 + tm * 16 + g;
                    s_fin[wn * 128 + lr] = p[tm][0];
                    s_fin[wn * 128 + lr + 8] = p[tm][1];
                }
            }
            __syncthreads();
            if (tid < 128) {
                const int R = blockIdx.x * 128 + tid;
                if (R < n) {
                    const float z = s_fin[tid] + s_fin[128 + tid] + s_c[1280];
                    out[R] = __fdividef(1.0f, 1.0f + __expf(-z));
                }
            }
        }
    }
}

// ===================== launch =====================
extern "C" void kernel_launch(void* const* d_in, const int* in_sizes, int n_in,
                              void* d_out, int out_size) {
    const float* x   = (const float*)d_in[0];
    const float* fy0 = (const float*)d_in[1];
    const float* u0  = (const float*)d_in[2];
    const float* w0  = (const float*)d_in[3];
    const float* la0 = (const float*)d_in[4];
    const float* b0  = (const float*)d_in[5];
    const float* uM  = (const float*)d_in[6];
    const float* wM  = (const float*)d_in[7];
    const float* laM = (const float*)d_in[8];
    const float* bM  = (const float*)d_in[9];
    const float* uL  = (const float*)d_in[10];
    // d_in[11] = wL: softmax of a [1,1] row == 1.0 (identity)
    const float* laL = (const float*)d_in[12];
    const float* bL  = (const float*)d_in[13];
    const float* W1  = (const float*)d_in[14];
    const float* b1  = (const float*)d_in[15];
    const float* W2  = (const float*)d_in[16];
    const float* b2  = (const float*)d_in[17];
    const float* W3  = (const float*)d_in[18];
    const float* b3  = (const float*)d_in[19];
    float* out = (float*)d_out;
    const int n = in_sizes[0];

    const int prep2_smem = (16384 + 2048) * 4;  // 73728
    const int fused_smem = 24576 * 4;           // 98304: 32KB Apack + 2x32KB wbuf
    cudaFuncSetAttribute(prep2_kernel, cudaFuncAttributeMaxDynamicSharedMemorySize, prep2_smem);
    cudaFuncSetAttribute(fused_kernel, cudaFuncAttributeMaxDynamicSharedMemorySize, fused_smem);

    prep1_kernel<<<417, 128>>>(u0, w0, la0, b0, uM, wM, laM, bM, uL, laL, bL);
    prep2_kernel<<<49, 256, prep2_smem>>>();
    fused_kernel<<<(n + 127) / 128, 256, fused_smem>>>(x, fy0, W1, b1, W2, b2, W3, b3, out, n);
}